// round 13
// baseline (speedup 1.0000x reference)
#include <cuda_runtime.h>
#include <cuda_fp16.h>
#include <math.h>
#include <stdint.h>

// ---------------- problem constants ----------------
#define NTOK   50176          // 16*56*56
#define BATCH  16
#define HH     56
#define WW     56
#define DMODEL 384
#define NHEAD  12
#define DHEAD  32
#define FFDIM  1536
#define WSZ    8
#define NWIN   49             // 7*7
#define LRED   49
#define QKVN   1152
#define CONVK  24576          // 8*8*384
#define SPLITK 16
#define SCALE  0.17677669529663687f   // 1/sqrt(32)

// ---------------- epilogue kinds ----------------
#define E_BIAS 0
#define E_SILU 1
#define E_RES  2
#define E_PART 3

// ---------------- scratch (static device memory; no allocs allowed) ----------------
__device__ float  g_KV[(size_t)BATCH * LRED * 2 * DMODEL];   // kv out (fp32, read by gattn)
__device__ float  g_PART[(size_t)SPLITK * BATCH * NWIN * DMODEL];

__device__ __align__(256) __half g_S0h[(size_t)NTOK * QKVN];     // qkv out (fp16)
__device__ __align__(256) __half g_S1h[(size_t)NTOK * DMODEL];   // LN out
__device__ __align__(256) __half g_S2h[(size_t)NTOK * DMODEL];   // wattn out / q
__device__ __align__(256) __half g_H16[(size_t)NTOK * FFDIM];    // ffn hidden / gattn out
__device__ __align__(256) __half g_S3h[(size_t)BATCH * NWIN * CONVK]; // im2col
__device__ __align__(256) __half g_Rh [(size_t)BATCH * LRED * DMODEL];

// transposed fp16 weights: layout [N][K]
__device__ __align__(256) __half g_qkvW[1152 * 384];
__device__ __align__(256) __half g_loW [384 * 384];
__device__ __align__(256) __half g_f1lW[1536 * 384];
__device__ __align__(256) __half g_f2lW[384 * 1536];
__device__ __align__(256) __half g_qW  [384 * 384];
__device__ __align__(256) __half g_kvW [768 * 384];
__device__ __align__(256) __half g_cvW [(size_t)384 * 24576];
__device__ __align__(256) __half g_goW [384 * 384];
__device__ __align__(256) __half g_f1gW[1536 * 384];
__device__ __align__(256) __half g_f2gW[384 * 1536];

// ---------------- helpers ----------------
__device__ __forceinline__ uint32_t smem_u32(const void* p) {
    uint32_t a;
    asm("{ .reg .u64 t; cvta.to.shared.u64 t, %1; cvt.u32.u64 %0, t; }" : "=r"(a) : "l"(p));
    return a;
}
#define SWZ128(off) ((off) ^ (((off) >> 3) & 0x70))

// .cg: L2-only staging (tiles are consumed from SMEM; L1 fill is pure pollution)
#define CPA16(dst, src) \
    asm volatile("cp.async.cg.shared.global [%0], [%1], 16;" :: "r"(dst), "l"(src))
#define CPCOMMIT() asm volatile("cp.async.commit_group;" ::: "memory")
#define CPWAIT1()  asm volatile("cp.async.wait_group 1;" ::: "memory")
#define CPWAIT0()  asm volatile("cp.async.wait_group 0;" ::: "memory")

#define LDSM4(r, adr)                                                             \
    asm volatile("ldmatrix.sync.aligned.m8n8.x4.shared.b16 {%0,%1,%2,%3}, [%4];"  \
        : "=r"((r)[0]), "=r"((r)[1]), "=r"((r)[2]), "=r"((r)[3]) : "r"(adr))

// mma.sync m16n8k16 fp16 -> fp32 (baseline sm_80+ PTX; compiles on compute_103)
#define MMA16816(c, a, b0v, b1v)                                                  \
    asm volatile("mma.sync.aligned.m16n8k16.row.col.f32.f16.f16.f32 "             \
        "{%0,%1,%2,%3}, {%4,%5,%6,%7}, {%8,%9}, {%0,%1,%2,%3};"                   \
        : "+f"((c)[0]), "+f"((c)[1]), "+f"((c)[2]), "+f"((c)[3])                  \
        : "r"((a)[0]), "r"((a)[1]), "r"((a)[2]), "r"((a)[3]), "r"(b0v), "r"(b1v))

// ---------------- weight transpose + fp16 cast: W[K,N] -> [N,K] ------------
__global__ void tconv_kernel(const float* __restrict__ W, __half* __restrict__ hi, int K, int N)
{
    __shared__ float t[32][33];
    int n0 = blockIdx.x * 32, k0 = blockIdx.y * 32;
    int tx = threadIdx.x, ty = threadIdx.y;      // 32 x 8
#pragma unroll
    for (int i = 0; i < 4; i++)
        t[ty + 8 * i][tx] = W[(size_t)(k0 + ty + 8 * i) * N + n0 + tx];
    __syncthreads();
#pragma unroll
    for (int i = 0; i < 4; i++) {
        int n = n0 + ty + 8 * i, k = k0 + tx;
        hi[(size_t)n * K + k] = __float2half_rn(t[tx][ty + 8 * i]);
    }
}

// ---------------- HMMA GEMM: C[M,N] = A[M,K](fp16) @ WT[N,K](fp16) --------------
// CTA tile 256x128, BK=32, 8 warps (4x2), warp tile 64x64 (4x8 m16n8k16).
// MMA:LDSM ratio 32:8 (vs 16:6 at 64x32) -> shared-pipe traffic per MMA x0.67.
// 3-buffer cp.async pipeline, single __syncthreads per chunk (refill targets the
// buffer consumed at t-1, proven drained by the barrier at t).
#define O_A     0
#define O_B     16384
#define HBUF    24576
#define NSTAGE  3
#define HG_SMEM (NSTAGE * HBUF)     // 73728

template <int EPI, typename OutT>
__global__ __launch_bounds__(256, 1)
void hgemm(const __half* __restrict__ A, const __half* __restrict__ B,
           const float* __restrict__ bias, const float* __restrict__ res,
           OutT* __restrict__ C, int M, int K, int ldc, int kSplit)
{
    extern __shared__ __align__(1024) char smem[];
    const uint32_t sb = smem_u32(smem);
    const int tid = threadIdx.x;
    const int wid = tid >> 5, lane = tid & 31;
    const int bm = blockIdx.y * 256;
    const int bn = blockIdx.x * 128;

    const int kPer   = K / kSplit;
    const int k0base = (EPI == E_PART) ? blockIdx.z * kPer : 0;
    const int kLen   = (EPI == E_PART) ? kPer : K;
    const int nch    = kLen / 32;                 // always >= 12

    // ---- loader mapping ----
    // A: 256 rows x 32 k (16KB). thread t -> row t, 4x16B cp.async.
    // B: 128 rows x 32 k (8KB).  thread t -> row t>>1, seg t&1, 2x16B cp.async.
    int am = bm + tid; if (am >= M) am = M - 1;
    const __half* aP = A + (size_t)am * K + k0base;
    const int brow = tid >> 1, bseg = tid & 1;
    const __half* bP = B + (size_t)(bn + brow) * K + k0base + bseg * 16;
    uint32_t swA[4];
#pragma unroll
    for (int j = 0; j < 4; j++) swA[j] = SWZ128((uint32_t)(tid * 64 + j * 16));
    const uint32_t swB0 = SWZ128((uint32_t)(brow * 64 + bseg * 32));
    const uint32_t swB1 = SWZ128((uint32_t)(brow * 64 + bseg * 32 + 16));

#define ISSUE(ci, bufbase) do {                                                   \
        const __half* _a = aP + (size_t)(ci) * 32;                                \
        const __half* _b = bP + (size_t)(ci) * 32;                                \
        CPA16((bufbase) + O_A + swA[0], _a);      CPA16((bufbase) + O_A + swA[1], _a + 8);  \
        CPA16((bufbase) + O_A + swA[2], _a + 16); CPA16((bufbase) + O_A + swA[3], _a + 24); \
        CPA16((bufbase) + O_B + swB0, _b);        CPA16((bufbase) + O_B + swB1, _b + 8);    \
        CPCOMMIT();                                                               \
    } while (0)

    // ---- warp tiling: 4 M-warps x 2 N-warps, each 64x64 ----
    const int warpM = (wid >> 1) * 64;
    const int warpN = (wid & 1) * 64;
    const int lrow = lane & 7, quad = lane >> 3;

    float acc[4][8][4];
#pragma unroll
    for (int i = 0; i < 4; i++)
#pragma unroll
        for (int j = 0; j < 8; j++)
#pragma unroll
            for (int c = 0; c < 4; c++) acc[i][j][c] = 0.f;

    // prologue: stage chunks 0 and 1
    ISSUE(0, sb);
    ISSUE(1, sb + HBUF);

    int bufIdx = 0;
    for (int t = 0; t < nch; t++) {
        if (t + 1 < nch) CPWAIT1(); else CPWAIT0();
        __syncthreads();

        // refill the buffer consumed at iteration t-1 (safe: sync above covers it)
        if (t + 2 < nch) {
            int nb = bufIdx + 2; if (nb >= NSTAGE) nb -= NSTAGE;
            ISSUE(t + 2, sb + (uint32_t)nb * HBUF);
        }

        const uint32_t buf = sb + (uint32_t)bufIdx * HBUF;
#pragma unroll
        for (int ks = 0; ks < 2; ks++) {
            const int ksB = ks * 32;
            uint32_t Ah[4][4], Bh[4][4];
            const int aRow = warpM + (quad & 1) * 8 + lrow;
            const int aKB  = ksB + (quad >> 1) * 16;
#pragma unroll
            for (int mt = 0; mt < 4; mt++) {
                uint32_t off = SWZ128((uint32_t)((aRow + mt * 16) * 64 + aKB));
                LDSM4(Ah[mt], buf + O_A + off);
            }
            const int bRow = warpN + (quad >> 1) * 8 + lrow;
            const int bKB  = ksB + (quad & 1) * 16;
#pragma unroll
            for (int nt2 = 0; nt2 < 4; nt2++) {
                uint32_t off = SWZ128((uint32_t)((bRow + nt2 * 16) * 64 + bKB));
                LDSM4(Bh[nt2], buf + O_B + off);
            }
#pragma unroll
            for (int mt = 0; mt < 4; mt++)
#pragma unroll
                for (int nt = 0; nt < 8; nt++) {
                    uint32_t b0 = Bh[nt >> 1][(nt & 1) * 2], b1 = Bh[nt >> 1][(nt & 1) * 2 + 1];
                    MMA16816(acc[mt][nt], Ah[mt], b0, b1);
                }
        }
        bufIdx = (bufIdx + 1 == NSTAGE) ? 0 : bufIdx + 1;
    }

    // ---- epilogue: c0,c1 -> (row g, n 2u..2u+1); c2,c3 -> (row g+8) ----
    const int g = lane >> 2, u = lane & 3;
    OutT* Cb = (EPI == E_PART) ? (C + (size_t)blockIdx.z * M * ldc) : C;
#pragma unroll
    for (int mt = 0; mt < 4; mt++) {
#pragma unroll
        for (int nt = 0; nt < 8; nt++) {
            const int gn = bn + warpN + nt * 8 + 2 * u;
#pragma unroll
            for (int h = 0; h < 2; h++) {
                const int gm = bm + warpM + mt * 16 + g + h * 8;
                if (gm < M) {
                    float v0 = acc[mt][nt][h * 2 + 0];
                    float v1 = acc[mt][nt][h * 2 + 1];
                    if (EPI != E_PART && bias != nullptr) {
                        float2 bv = *(const float2*)(bias + gn);
                        v0 += bv.x; v1 += bv.y;
                    }
                    if (EPI == E_SILU) {
                        v0 = v0 / (1.f + __expf(-v0));
                        v1 = v1 / (1.f + __expf(-v1));
                    }
                    if (EPI == E_RES) {
                        float2 rv = *(const float2*)(res + (size_t)gm * ldc + gn);
                        v0 += rv.x; v1 += rv.y;
                    }
                    if constexpr (sizeof(OutT) == 2) {
                        *(__half2*)((__half*)Cb + (size_t)gm * ldc + gn) =
                            __halves2half2(__float2half_rn(v0), __float2half_rn(v1));
                    } else {
                        *(float2*)((float*)Cb + (size_t)gm * ldc + gn) = make_float2(v0, v1);
                    }
                }
            }
        }
    }
#undef ISSUE
}

// ---------------- LayerNorm: one warp per token, fp16 output ----------------
__global__ void ln_kernel(const float* __restrict__ x, const float* __restrict__ g,
                          const float* __restrict__ be, __half* __restrict__ y)
{
    int gw = (blockIdx.x * blockDim.x + threadIdx.x) >> 5;
    int lane = threadIdx.x & 31;
    if (gw >= NTOK) return;
    const float4* xr = (const float4*)(x + (size_t)gw * DMODEL);
    float4 v0 = xr[lane], v1 = xr[32 + lane], v2 = xr[64 + lane];
    float s = v0.x + v0.y + v0.z + v0.w + v1.x + v1.y + v1.z + v1.w + v2.x + v2.y + v2.z + v2.w;
#pragma unroll
    for (int o = 16; o; o >>= 1) s += __shfl_xor_sync(0xffffffffu, s, o);
    float m = s * (1.f / 384.f);
    float q = 0.f;
    {
        float d;
        d = v0.x - m; q += d * d; d = v0.y - m; q += d * d; d = v0.z - m; q += d * d; d = v0.w - m; q += d * d;
        d = v1.x - m; q += d * d; d = v1.y - m; q += d * d; d = v1.z - m; q += d * d; d = v1.w - m; q += d * d;
        d = v2.x - m; q += d * d; d = v2.y - m; q += d * d; d = v2.z - m; q += d * d; d = v2.w - m; q += d * d;
    }
#pragma unroll
    for (int o = 16; o; o >>= 1) q += __shfl_xor_sync(0xffffffffu, q, o);
    float inv = rsqrtf(q * (1.f / 384.f) + 1e-6f);
    const float4* gp = (const float4*)g;
    const float4* bp = (const float4*)be;
    __half2* yr = (__half2*)(y + (size_t)gw * DMODEL);
#pragma unroll
    for (int s2 = 0; s2 < 3; s2++) {
        float4 vv = (s2 == 0) ? v0 : (s2 == 1) ? v1 : v2;
        float4 gg = gp[s2 * 32 + lane];
        float4 bb = bp[s2 * 32 + lane];
        float o0 = (vv.x - m) * inv * gg.x + bb.x;
        float o1 = (vv.y - m) * inv * gg.y + bb.y;
        float o2 = (vv.z - m) * inv * gg.z + bb.z;
        float o3 = (vv.w - m) * inv * gg.w + bb.w;
        yr[s2 * 64 + lane * 2 + 0] = __halves2half2(__float2half_rn(o0), __float2half_rn(o1));
        yr[s2 * 64 + lane * 2 + 1] = __halves2half2(__float2half_rn(o2), __float2half_rn(o3));
    }
}

// ---------------- windowed local attention: qkv fp16 in, fp16 out ------------
__global__ __launch_bounds__(256) void wattn_kernel(const __half* __restrict__ qkv, __half* __restrict__ o)
{
    const int bid  = blockIdx.x;
    const int head = bid % NHEAD;
    const int win  = (bid / NHEAD) % NWIN;
    const int b    = bid / (NHEAD * NWIN);
    const int wy = win / 7, wx = win % 7;
    const int tid = threadIdx.x;

    __shared__ float qs[64 * 36], ksm[64 * 36], vsm[64 * 36], Ss[64 * 65];

    {
        int tok = tid >> 2, d0 = (tid & 3) * 8;
        int grow = (b * HH + wy * WSZ + (tok >> 3)) * WW + wx * WSZ + (tok & 7);
        const __half* base = qkv + (size_t)grow * QKVN + head * DHEAD + d0;
#pragma unroll
        for (int which = 0; which < 3; which++) {
            const __half2* src = (const __half2*)(base + which * 384);
            float* dst = (which == 0 ? qs : which == 1 ? ksm : vsm) + tok * 36 + d0;
#pragma unroll
            for (int j = 0; j < 4; j++) {
                float2 f = __half22float2(src[j]);
                dst[j * 2] = f.x; dst[j * 2 + 1] = f.y;
            }
        }
    }
    __syncthreads();

    for (int idx = tid; idx < 4096; idx += 256) {
        int r = idx >> 6, c = idx & 63;
        float s = 0.f;
#pragma unroll
        for (int d = 0; d < 32; d += 4) {
            float4 qq = *(const float4*)&qs[r * 36 + d];
            float4 kk = *(const float4*)&ksm[c * 36 + d];
            s += qq.x * kk.x + qq.y * kk.y + qq.z * kk.z + qq.w * kk.w;
        }
        Ss[r * 65 + c] = s * SCALE;
    }
    __syncthreads();

    const int r = tid >> 2, l4 = tid & 3;
    float mx = -1e30f;
    for (int c = l4; c < 64; c += 4) mx = fmaxf(mx, Ss[r * 65 + c]);
    mx = fmaxf(mx, __shfl_xor_sync(0xffffffffu, mx, 1));
    mx = fmaxf(mx, __shfl_xor_sync(0xffffffffu, mx, 2));
    float sum = 0.f;
    for (int c = l4; c < 64; c += 4) { float e = __expf(Ss[r * 65 + c] - mx); Ss[r * 65 + c] = e; sum += e; }
    sum += __shfl_xor_sync(0xffffffffu, sum, 1);
    sum += __shfl_xor_sync(0xffffffffu, sum, 2);
    float inv = 1.f / sum;
    __syncwarp();

    float o0[8];
#pragma unroll
    for (int j = 0; j < 8; j++) o0[j] = 0.f;
    for (int c = 0; c < 64; c++) {
        float p = Ss[r * 65 + c];
        float4 va = *(const float4*)&vsm[c * 36 + l4 * 8];
        float4 vb = *(const float4*)&vsm[c * 36 + l4 * 8 + 4];
        o0[0] += p * va.x; o0[1] += p * va.y; o0[2] += p * va.z; o0[3] += p * va.w;
        o0[4] += p * vb.x; o0[5] += p * vb.y; o0[6] += p * vb.z; o0[7] += p * vb.w;
    }
    size_t orow = ((size_t)(b * HH + wy * WSZ + (r >> 3)) * WW + wx * WSZ + (r & 7)) * DMODEL
                  + head * DHEAD + l4 * 8;
    __half2* op = (__half2*)(o + orow);
#pragma unroll
    for (int j = 0; j < 4; j++)
        op[j] = __halves2half2(__float2half_rn(o0[j * 2] * inv), __float2half_rn(o0[j * 2 + 1] * inv));
}

// ---------------- im2col (stride == kernel: pure permutation), fp16 ----------------
__global__ void im2col_kernel(const __half* __restrict__ y, __half* __restrict__ out)
{
    size_t idx = (size_t)blockIdx.x * 256 + threadIdx.x;
    if (idx >= (size_t)BATCH * NWIN * CONVK) return;
    int m = (int)(idx / CONVK), kk = (int)(idx % CONVK);
    int pos = kk / DMODEL, c = kk % DMODEL;
    int i = pos >> 3, j = pos & 7;
    int b = m / NWIN, win = m % NWIN, wy = win / 7, wx = win % 7;
    out[idx] = y[((size_t)(b * HH + wy * WSZ + i) * WW + wx * WSZ + j) * DMODEL + c];
}

// ---------------- split-K reduction + conv bias, fp16 out ----------------
__global__ void reduce_part_kernel(const float* __restrict__ part, const float* __restrict__ bias,
                                   __half* __restrict__ R)
{
    int idx = blockIdx.x * 256 + threadIdx.x;
    if (idx >= BATCH * NWIN * DMODEL) return;
    float s = bias[idx % DMODEL];
    const size_t stride = (size_t)BATCH * NWIN * DMODEL;
#pragma unroll
    for (int z = 0; z < SPLITK; z++) s += part[(size_t)z * stride + idx];
    R[idx] = __float2half_rn(s);
}

// ---------------- global attention: q fp16, kv fp32, out fp16 ----------------
__global__ __launch_bounds__(128) void gattn_kernel(const __half* __restrict__ q,
                                                    const float* __restrict__ kv,
                                                    __half* __restrict__ o)
{
    const int b = blockIdx.z, h = blockIdx.y;
    const int tid = threadIdx.x;
    __shared__ float ks[LRED * DHEAD], vs[LRED * DHEAD];
    for (int idx = tid; idx < LRED * DHEAD; idx += 128) {
        int l = idx >> 5, d = idx & 31;
        size_t base = (size_t)(b * LRED + l) * (2 * DMODEL) + h * DHEAD + d;
        ks[idx] = kv[base];
        vs[idx] = kv[base + DMODEL];
    }
    __syncthreads();
    int t = blockIdx.x * 128 + tid;
    if (t >= HH * WW) return;
    const __half2* qr = (const __half2*)(q + ((size_t)b * (HH * WW) + t) * DMODEL + h * DHEAD);
    float qv[32];
#pragma unroll
    for (int d = 0; d < 16; d++) {
        float2 f = __half22float2(qr[d]);
        qv[d * 2] = f.x; qv[d * 2 + 1] = f.y;
    }
    float s[LRED];
    float mx = -1e30f;
#pragma unroll
    for (int l = 0; l < LRED; l++) {
        float acc = 0.f;
#pragma unroll
        for (int d = 0; d < 32; d++) acc += qv[d] * ks[l * 32 + d];
        acc *= SCALE;
        s[l] = acc;
        mx = fmaxf(mx, acc);
    }
    float sum = 0.f;
#pragma unroll
    for (int l = 0; l < LRED; l++) { s[l] = __expf(s[l] - mx); sum += s[l]; }
    float inv = 1.f / sum;
    float ov[32];
#pragma unroll
    for (int d = 0; d < 32; d++) ov[d] = 0.f;
#pragma unroll
    for (int l = 0; l < LRED; l++) {
        float p = s[l];
#pragma unroll
        for (int d = 0; d < 32; d++) ov[d] += p * vs[l * 32 + d];
    }
    __half2* orow = (__half2*)(o + ((size_t)b * (HH * WW) + t) * DMODEL + h * DHEAD);
#pragma unroll
    for (int d = 0; d < 16; d++)
        orow[d] = __halves2half2(__float2half_rn(ov[d * 2] * inv), __float2half_rn(ov[d * 2 + 1] * inv));
}

// ---------------- host orchestration ----------------
static void launch_tconv(const float* W, __half* arr, int K, int N) {
    tconv_kernel<<<dim3(N / 32, K / 32), dim3(32, 8)>>>(W, arr, K, N);
}

extern "C" void kernel_launch(void* const* d_in, const int* in_sizes, int n_in,
                              void* d_out_v, int out_size)
{
    const float* x      = (const float*)d_in[0];
    const float* g1     = (const float*)d_in[1];
    const float* be1    = (const float*)d_in[2];
    const float* w_qkv  = (const float*)d_in[3];
    const float* b_qkv  = (const float*)d_in[4];
    const float* w_lo   = (const float*)d_in[5];
    const float* b_lo   = (const float*)d_in[6];
    const float* g2     = (const float*)d_in[7];
    const float* be2    = (const float*)d_in[8];
    const float* w_f1l  = (const float*)d_in[9];
    const float* b_f1l  = (const float*)d_in[10];
    const float* w_f2l  = (const float*)d_in[11];
    const float* b_f2l  = (const float*)d_in[12];
    const float* g3     = (const float*)d_in[13];
    const float* be3    = (const float*)d_in[14];
    const float* w_q    = (const float*)d_in[15];
    const float* w_kv   = (const float*)d_in[16];
    const float* conv_w = (const float*)d_in[17];
    const float* conv_b = (const float*)d_in[18];
    const float* w_go   = (const float*)d_in[19];
    const float* b_go   = (const float*)d_in[20];
    const float* g4     = (const float*)d_in[21];
    const float* be4    = (const float*)d_in[22];
    const float* w_f1g  = (const float*)d_in[23];
    const float* b_f1g  = (const float*)d_in[24];
    const float* w_f2g  = (const float*)d_in[25];
    const float* b_f2g  = (const float*)d_in[26];
    float* out = (float*)d_out_v;

    float *KV, *PART;
    __half *S0h, *S1h, *S2h, *H16, *S3h, *Rh;
    cudaGetSymbolAddress((void**)&KV, g_KV);
    cudaGetSymbolAddress((void**)&PART, g_PART);
    cudaGetSymbolAddress((void**)&S0h, g_S0h);
    cudaGetSymbolAddress((void**)&S1h, g_S1h);
    cudaGetSymbolAddress((void**)&S2h, g_S2h);
    cudaGetSymbolAddress((void**)&H16, g_H16);
    cudaGetSymbolAddress((void**)&S3h, g_S3h);
    cudaGetSymbolAddress((void**)&Rh,  g_Rh);
    __half *WqkvT, *WloT, *Wf1lT, *Wf2lT, *WqT, *WkvT, *WcvT, *WgoT, *Wf1gT, *Wf2gT;
    cudaGetSymbolAddress((void**)&WqkvT, g_qkvW);
    cudaGetSymbolAddress((void**)&WloT,  g_loW);
    cudaGetSymbolAddress((void**)&Wf1lT, g_f1lW);
    cudaGetSymbolAddress((void**)&Wf2lT, g_f2lW);
    cudaGetSymbolAddress((void**)&WqT,   g_qW);
    cudaGetSymbolAddress((void**)&WkvT,  g_kvW);
    cudaGetSymbolAddress((void**)&WcvT,  g_cvW);
    cudaGetSymbolAddress((void**)&WgoT,  g_goW);
    cudaGetSymbolAddress((void**)&Wf1gT, g_f1gW);
    cudaGetSymbolAddress((void**)&Wf2gT, g_f2gW);

    cudaFuncSetAttribute(hgemm<E_BIAS, float>,  cudaFuncAttributeMaxDynamicSharedMemorySize, HG_SMEM);
    cudaFuncSetAttribute(hgemm<E_BIAS, __half>, cudaFuncAttributeMaxDynamicSharedMemorySize, HG_SMEM);
    cudaFuncSetAttribute(hgemm<E_SILU, __half>, cudaFuncAttributeMaxDynamicSharedMemorySize, HG_SMEM);
    cudaFuncSetAttribute(hgemm<E_RES,  float>,  cudaFuncAttributeMaxDynamicSharedMemorySize, HG_SMEM);
    cudaFuncSetAttribute(hgemm<E_PART, float>,  cudaFuncAttributeMaxDynamicSharedMemorySize, HG_SMEM);

    const int MB  = NTOK / 256;                    // 196 (M tiles of 256)
    const int MBS = (BATCH * NWIN + 255) / 256;    // 4 (conv / kv GEMMs, M=784)
    dim3 blk(256);

    // launch order: our #4 (= likely overall #6 under ncu -s 5 -c 1) is the qkv hgemm
    launch_tconv(w_qkv,  WqkvT, DMODEL, QKVN);          // 1
    launch_tconv(w_lo,   WloT,  DMODEL, DMODEL);        // 2
    ln_kernel<<<NTOK / 8, 256>>>(x, g1, be1, S1h);      // 3

    // ---- block 1: local attention ----
    hgemm<E_BIAS, __half><<<dim3(QKVN / 128, MB, 1), blk, HG_SMEM>>>(   // 4
        S1h, WqkvT, b_qkv, nullptr, S0h, NTOK, DMODEL, QKVN, 1);
    wattn_kernel<<<BATCH * NWIN * NHEAD, 256>>>(S0h, S2h);
    hgemm<E_RES, float><<<dim3(DMODEL / 128, MB, 1), blk, HG_SMEM>>>(
        S2h, WloT, b_lo, x, out, NTOK, DMODEL, DMODEL, 1);

    // ---- block 2: local FFN ----
    launch_tconv(w_f1l,  Wf1lT, DMODEL, FFDIM);
    launch_tconv(w_f2l,  Wf2lT, FFDIM,  DMODEL);
    ln_kernel<<<NTOK / 8, 256>>>(out, g2, be2, S1h);
    hgemm<E_SILU, __half><<<dim3(FFDIM / 128, MB, 1), blk, HG_SMEM>>>(
        S1h, Wf1lT, b_f1l, nullptr, H16, NTOK, DMODEL, FFDIM, 1);
    hgemm<E_RES, float><<<dim3(DMODEL / 128, MB, 1), blk, HG_SMEM>>>(
        H16, Wf2lT, b_f2l, out, out, NTOK, FFDIM, DMODEL, 1);

    // remaining weight prep (before block 3 uses them)
    launch_tconv(w_q,    WqT,   DMODEL, DMODEL);
    launch_tconv(w_kv,   WkvT,  DMODEL, 2 * DMODEL);
    launch_tconv(conv_w, WcvT,  CONVK,  DMODEL);
    launch_tconv(w_go,   WgoT,  DMODEL, DMODEL);
    launch_tconv(w_f1g,  Wf1gT, DMODEL, FFDIM);
    launch_tconv(w_f2g,  Wf2gT, FFDIM,  DMODEL);

    // ---- block 3: global attention ----
    ln_kernel<<<NTOK / 8, 256>>>(out, g3, be3, S1h);
    hgemm<E_BIAS, __half><<<dim3(DMODEL / 128, MB, 1), blk, HG_SMEM>>>(
        S1h, WqT, nullptr, nullptr, S2h, NTOK, DMODEL, DMODEL, 1);
    {
        size_t tot = (size_t)BATCH * NWIN * CONVK;
        im2col_kernel<<<(unsigned)((tot + 255) / 256), 256>>>(S1h, S3h);
    }
    hgemm<E_PART, float><<<dim3(DMODEL / 128, MBS, SPLITK), blk, HG_SMEM>>>(
        S3h, WcvT, nullptr, nullptr, PART, BATCH * NWIN, CONVK, DMODEL, SPLITK);
    reduce_part_kernel<<<(BATCH * NWIN * DMODEL + 255) / 256, 256>>>(PART, conv_b, Rh);
    hgemm<E_BIAS, float><<<dim3((2 * DMODEL) / 128, MBS, 1), blk, HG_SMEM>>>(
        Rh, WkvT, nullptr, nullptr, KV, BATCH * LRED, DMODEL, 2 * DMODEL, 1);
    gattn_kernel<<<dim3((HH * WW + 127) / 128, NHEAD, BATCH), 128>>>(S2h, KV, H16);
    hgemm<E_RES, float><<<dim3(DMODEL / 128, MB, 1), blk, HG_SMEM>>>(
        H16, WgoT, b_go, out, out, NTOK, DMODEL, DMODEL, 1);

    // ---- block 4: global FFN ----
    ln_kernel<<<NTOK / 8, 256>>>(out, g4, be4, S1h);
    hgemm<E_SILU, __half><<<dim3(FFDIM / 128, MB, 1), blk, HG_SMEM>>>(
        S1h, Wf1gT, b_f1g, nullptr, H16, NTOK, DMODEL, FFDIM, 1);
    hgemm<E_RES, float><<<dim3(DMODEL / 128, MB, 1), blk, HG_SMEM>>>(
        H16, Wf2gT, b_f2g, out, out, NTOK, FFDIM, DMODEL, 1);
}

// round 14
// speedup vs baseline: 1.1493x; 1.1493x over previous
#include <cuda_runtime.h>
#include <cuda_fp16.h>
#include <math.h>
#include <stdint.h>

// ---------------- problem constants ----------------
#define NTOK   50176          // 16*56*56
#define BATCH  16
#define HH     56
#define WW     56
#define DMODEL 384
#define NHEAD  12
#define DHEAD  32
#define FFDIM  1536
#define WSZ    8
#define NWIN   49             // 7*7
#define LRED   49
#define QKVN   1152
#define CONVK  24576          // 8*8*384
#define SPLITK 8
#define SCALE  0.17677669529663687f   // 1/sqrt(32)

// ---------------- epilogue kinds ----------------
#define E_BIAS 0
#define E_SILU 1
#define E_RES  2
#define E_PART 3

// ---------------- scratch (static device memory; no allocs allowed) ----------------
__device__ float  g_KV[(size_t)BATCH * LRED * 2 * DMODEL];   // kv out (fp32, read by gattn)
__device__ float  g_PART[(size_t)SPLITK * BATCH * NWIN * DMODEL];

__device__ __align__(256) __half g_S0h[(size_t)NTOK * QKVN];     // qkv out (fp16)
__device__ __align__(256) __half g_S1h[(size_t)NTOK * DMODEL];   // LN out
__device__ __align__(256) __half g_S2h[(size_t)NTOK * DMODEL];   // wattn out / q
__device__ __align__(256) __half g_H16[(size_t)NTOK * FFDIM];    // ffn hidden / gattn out
__device__ __align__(256) __half g_S3h[(size_t)BATCH * NWIN * CONVK]; // im2col
__device__ __align__(256) __half g_Rh [(size_t)BATCH * LRED * DMODEL];

// transposed fp16 weights: layout [N][K]
__device__ __align__(256) __half g_qkvW[1152 * 384];
__device__ __align__(256) __half g_loW [384 * 384];
__device__ __align__(256) __half g_f1lW[1536 * 384];
__device__ __align__(256) __half g_f2lW[384 * 1536];
__device__ __align__(256) __half g_qW  [384 * 384];
__device__ __align__(256) __half g_kvW [768 * 384];
__device__ __align__(256) __half g_cvW [(size_t)384 * 24576];
__device__ __align__(256) __half g_goW [384 * 384];
__device__ __align__(256) __half g_f1gW[1536 * 384];
__device__ __align__(256) __half g_f2gW[384 * 1536];

// ---------------- helpers ----------------
__device__ __forceinline__ uint32_t smem_u32(const void* p) {
    uint32_t a;
    asm("{ .reg .u64 t; cvta.to.shared.u64 t, %1; cvt.u32.u64 %0, t; }" : "=r"(a) : "l"(p));
    return a;
}
#define SWZ128(off) ((off) ^ (((off) >> 3) & 0x70))

// .cg: L2-only staging (tiles are consumed from SMEM; L1 fill is pure pollution)
#define CPA16(dst, src) \
    asm volatile("cp.async.cg.shared.global [%0], [%1], 16;" :: "r"(dst), "l"(src))
#define CPCOMMIT() asm volatile("cp.async.commit_group;" ::: "memory")
#define CPWAIT1()  asm volatile("cp.async.wait_group 1;" ::: "memory")
#define CPWAIT0()  asm volatile("cp.async.wait_group 0;" ::: "memory")

#define LDSM4(r, adr)                                                             \
    asm volatile("ldmatrix.sync.aligned.m8n8.x4.shared.b16 {%0,%1,%2,%3}, [%4];"  \
        : "=r"((r)[0]), "=r"((r)[1]), "=r"((r)[2]), "=r"((r)[3]) : "r"(adr))

// mma.sync m16n8k16 fp16 -> fp32 (baseline sm_80+ PTX; compiles on compute_103)
#define MMA16816(c, a, b0v, b1v)                                                  \
    asm volatile("mma.sync.aligned.m16n8k16.row.col.f32.f16.f16.f32 "             \
        "{%0,%1,%2,%3}, {%4,%5,%6,%7}, {%8,%9}, {%0,%1,%2,%3};"                   \
        : "+f"((c)[0]), "+f"((c)[1]), "+f"((c)[2]), "+f"((c)[3])                  \
        : "r"((a)[0]), "r"((a)[1]), "r"((a)[2]), "r"((a)[3]), "r"(b0v), "r"(b1v))

// ---------------- weight transpose + fp16 cast: W[K,N] -> [N,K] ------------
__global__ void tconv_kernel(const float* __restrict__ W, __half* __restrict__ hi, int K, int N)
{
    __shared__ float t[32][33];
    int n0 = blockIdx.x * 32, k0 = blockIdx.y * 32;
    int tx = threadIdx.x, ty = threadIdx.y;      // 32 x 8
#pragma unroll
    for (int i = 0; i < 4; i++)
        t[ty + 8 * i][tx] = W[(size_t)(k0 + ty + 8 * i) * N + n0 + tx];
    __syncthreads();
#pragma unroll
    for (int i = 0; i < 4; i++) {
        int n = n0 + ty + 8 * i, k = k0 + tx;
        hi[(size_t)n * K + k] = __float2half_rn(t[tx][ty + 8 * i]);
    }
}

// ---------------- HMMA GEMM: C[M,N] = A[M,K](fp16) @ WT[N,K](fp16) --------------
// (exact R12 config: proven 184us on qkv) CTA 128x128, BK=32, 8 warps (2x4),
// warp tile 64x32 (4x4 m16n8k16), 3-buffer cp.async, single sync per chunk.
#define O_A     0
#define O_B     8192
#define HBUF    16384
#define NSTAGE  3
#define HG_SMEM (NSTAGE * HBUF)     // 49152

template <int EPI, typename OutT>
__global__ __launch_bounds__(256)
void hgemm(const __half* __restrict__ A, const __half* __restrict__ B,
           const float* __restrict__ bias, const float* __restrict__ res,
           OutT* __restrict__ C, int M, int K, int ldc, int kSplit)
{
    extern __shared__ __align__(1024) char smem[];
    const uint32_t sb = smem_u32(smem);
    const int tid = threadIdx.x;
    const int wid = tid >> 5, lane = tid & 31;
    const int bm = blockIdx.y * 128;
    const int bn = blockIdx.x * 128;

    const int kPer   = K / kSplit;
    const int k0base = (EPI == E_PART) ? blockIdx.z * kPer : 0;
    const int kLen   = (EPI == E_PART) ? kPer : K;
    const int nch    = kLen / 32;                 // always >= 12

    const int row = tid >> 1;
    const int seg = tid & 1;
    int am = bm + row; if (am >= M) am = M - 1;
    const __half* aP = A + (size_t)am * K + k0base + seg * 16;
    const __half* bP = B + (size_t)(bn + row) * K + k0base + seg * 16;
    const uint32_t sw0 = SWZ128((uint32_t)(row * 64 + seg * 32));
    const uint32_t sw1 = SWZ128((uint32_t)(row * 64 + seg * 32 + 16));

#define ISSUE(ci, bufbase) do {                                                   \
        const __half* _a = aP + (size_t)(ci) * 32;                                \
        const __half* _b = bP + (size_t)(ci) * 32;                                \
        CPA16((bufbase) + O_A + sw0, _a);  CPA16((bufbase) + O_A + sw1, _a + 8);  \
        CPA16((bufbase) + O_B + sw0, _b);  CPA16((bufbase) + O_B + sw1, _b + 8);  \
        CPCOMMIT();                                                               \
    } while (0)

    const int warpM = (wid >> 2) * 64;
    const int warpN = (wid & 3) * 32;
    const int lrow = lane & 7, quad = lane >> 3;

    float acc[4][4][4];
#pragma unroll
    for (int i = 0; i < 4; i++)
#pragma unroll
        for (int j = 0; j < 4; j++)
#pragma unroll
            for (int c = 0; c < 4; c++) acc[i][j][c] = 0.f;

    ISSUE(0, sb);
    ISSUE(1, sb + HBUF);

    int bufIdx = 0;
    for (int t = 0; t < nch; t++) {
        if (t + 1 < nch) CPWAIT1(); else CPWAIT0();
        __syncthreads();

        if (t + 2 < nch) {
            int nb = bufIdx + 2; if (nb >= NSTAGE) nb -= NSTAGE;
            ISSUE(t + 2, sb + (uint32_t)nb * HBUF);
        }

        const uint32_t buf = sb + (uint32_t)bufIdx * HBUF;
#pragma unroll
        for (int ks = 0; ks < 2; ks++) {
            const int ksB = ks * 32;
            uint32_t Ah[4][4], Bh[2][4];
            const int aRow = warpM + (quad & 1) * 8 + lrow;
            const int aKB  = ksB + (quad >> 1) * 16;
#pragma unroll
            for (int mt = 0; mt < 4; mt++) {
                uint32_t off = SWZ128((uint32_t)((aRow + mt * 16) * 64 + aKB));
                LDSM4(Ah[mt], buf + O_A + off);
            }
            const int bRow = warpN + (quad >> 1) * 8 + lrow;
            const int bKB  = ksB + (quad & 1) * 16;
#pragma unroll
            for (int nt2 = 0; nt2 < 2; nt2++) {
                uint32_t off = SWZ128((uint32_t)((bRow + nt2 * 16) * 64 + bKB));
                LDSM4(Bh[nt2], buf + O_B + off);
            }
#pragma unroll
            for (int mt = 0; mt < 4; mt++)
#pragma unroll
                for (int nt = 0; nt < 4; nt++) {
                    uint32_t b0 = Bh[nt >> 1][(nt & 1) * 2], b1 = Bh[nt >> 1][(nt & 1) * 2 + 1];
                    MMA16816(acc[mt][nt], Ah[mt], b0, b1);
                }
        }
        bufIdx = (bufIdx + 1 == NSTAGE) ? 0 : bufIdx + 1;
    }

    const int g = lane >> 2, u = lane & 3;
    OutT* Cb = (EPI == E_PART) ? (C + (size_t)blockIdx.z * M * ldc) : C;
#pragma unroll
    for (int mt = 0; mt < 4; mt++) {
#pragma unroll
        for (int nt = 0; nt < 4; nt++) {
            const int gn = bn + warpN + nt * 8 + 2 * u;
#pragma unroll
            for (int h = 0; h < 2; h++) {
                const int gm = bm + warpM + mt * 16 + g + h * 8;
                if (gm < M) {
                    float v0 = acc[mt][nt][h * 2 + 0];
                    float v1 = acc[mt][nt][h * 2 + 1];
                    if (EPI != E_PART && bias != nullptr) {
                        float2 bv = *(const float2*)(bias + gn);
                        v0 += bv.x; v1 += bv.y;
                    }
                    if (EPI == E_SILU) {
                        v0 = v0 / (1.f + __expf(-v0));
                        v1 = v1 / (1.f + __expf(-v1));
                    }
                    if (EPI == E_RES) {
                        float2 rv = *(const float2*)(res + (size_t)gm * ldc + gn);
                        v0 += rv.x; v1 += rv.y;
                    }
                    if constexpr (sizeof(OutT) == 2) {
                        *(__half2*)((__half*)Cb + (size_t)gm * ldc + gn) =
                            __halves2half2(__float2half_rn(v0), __float2half_rn(v1));
                    } else {
                        *(float2*)((float*)Cb + (size_t)gm * ldc + gn) = make_float2(v0, v1);
                    }
                }
            }
        }
    }
#undef ISSUE
}

// ---------------- LayerNorm: one warp per token, fp16 output ----------------
__global__ void ln_kernel(const float* __restrict__ x, const float* __restrict__ g,
                          const float* __restrict__ be, __half* __restrict__ y)
{
    int gw = (blockIdx.x * blockDim.x + threadIdx.x) >> 5;
    int lane = threadIdx.x & 31;
    if (gw >= NTOK) return;
    const float4* xr = (const float4*)(x + (size_t)gw * DMODEL);
    float4 v0 = xr[lane], v1 = xr[32 + lane], v2 = xr[64 + lane];
    float s = v0.x + v0.y + v0.z + v0.w + v1.x + v1.y + v1.z + v1.w + v2.x + v2.y + v2.z + v2.w;
#pragma unroll
    for (int o = 16; o; o >>= 1) s += __shfl_xor_sync(0xffffffffu, s, o);
    float m = s * (1.f / 384.f);
    float q = 0.f;
    {
        float d;
        d = v0.x - m; q += d * d; d = v0.y - m; q += d * d; d = v0.z - m; q += d * d; d = v0.w - m; q += d * d;
        d = v1.x - m; q += d * d; d = v1.y - m; q += d * d; d = v1.z - m; q += d * d; d = v1.w - m; q += d * d;
        d = v2.x - m; q += d * d; d = v2.y - m; q += d * d; d = v2.z - m; q += d * d; d = v2.w - m; q += d * d;
    }
#pragma unroll
    for (int o = 16; o; o >>= 1) q += __shfl_xor_sync(0xffffffffu, q, o);
    float inv = rsqrtf(q * (1.f / 384.f) + 1e-6f);
    const float4* gp = (const float4*)g;
    const float4* bp = (const float4*)be;
    __half2* yr = (__half2*)(y + (size_t)gw * DMODEL);
#pragma unroll
    for (int s2 = 0; s2 < 3; s2++) {
        float4 vv = (s2 == 0) ? v0 : (s2 == 1) ? v1 : v2;
        float4 gg = gp[s2 * 32 + lane];
        float4 bb = bp[s2 * 32 + lane];
        float o0 = (vv.x - m) * inv * gg.x + bb.x;
        float o1 = (vv.y - m) * inv * gg.y + bb.y;
        float o2 = (vv.z - m) * inv * gg.z + bb.z;
        float o3 = (vv.w - m) * inv * gg.w + bb.w;
        yr[s2 * 64 + lane * 2 + 0] = __halves2half2(__float2half_rn(o0), __float2half_rn(o1));
        yr[s2 * 64 + lane * 2 + 1] = __halves2half2(__float2half_rn(o2), __float2half_rn(o3));
    }
}

// ---------------- windowed local attention: qkv fp16 in, fp16 out ------------
// Score phase restructured: q row cached in registers; column map c = 4*c16 + l4
// (4 lanes of a row-group hit word-banks {+0,+4,+8,+12} -> conflict-free LDS.128
// with 8-way row broadcast; score writer lane == softmax reader lane).
__global__ __launch_bounds__(256) void wattn_kernel(const __half* __restrict__ qkv, __half* __restrict__ o)
{
    const int bid  = blockIdx.x;
    const int head = bid % NHEAD;
    const int win  = (bid / NHEAD) % NWIN;
    const int b    = bid / (NHEAD * NWIN);
    const int wy = win / 7, wx = win % 7;
    const int tid = threadIdx.x;

    __shared__ float qs[64 * 36], ksm[64 * 36], vsm[64 * 36], Ss[64 * 65];

    {
        int tok = tid >> 2, d0 = (tid & 3) * 8;
        int grow = (b * HH + wy * WSZ + (tok >> 3)) * WW + wx * WSZ + (tok & 7);
        const __half* base = qkv + (size_t)grow * QKVN + head * DHEAD + d0;
#pragma unroll
        for (int which = 0; which < 3; which++) {
            const __half2* src = (const __half2*)(base + which * 384);
            float* dst = (which == 0 ? qs : which == 1 ? ksm : vsm) + tok * 36 + d0;
#pragma unroll
            for (int j = 0; j < 4; j++) {
                float2 f = __half22float2(src[j]);
                dst[j * 2] = f.x; dst[j * 2 + 1] = f.y;
            }
        }
    }
    __syncthreads();

    const int r = tid >> 2, l4 = tid & 3;

    // ---- scores: q row in registers, 16 columns per thread ----
    {
        float4 q0 = *(const float4*)&qs[r * 36 + 0];
        float4 q1 = *(const float4*)&qs[r * 36 + 4];
        float4 q2 = *(const float4*)&qs[r * 36 + 8];
        float4 q3 = *(const float4*)&qs[r * 36 + 12];
        float4 q4 = *(const float4*)&qs[r * 36 + 16];
        float4 q5 = *(const float4*)&qs[r * 36 + 20];
        float4 q6 = *(const float4*)&qs[r * 36 + 24];
        float4 q7 = *(const float4*)&qs[r * 36 + 28];
#pragma unroll
        for (int c16 = 0; c16 < 16; c16++) {
            int c = c16 * 4 + l4;
            const float* kc = &ksm[c * 36];
            float4 k0 = *(const float4*)(kc + 0),  k1 = *(const float4*)(kc + 4);
            float4 k2 = *(const float4*)(kc + 8),  k3 = *(const float4*)(kc + 12);
            float4 k4 = *(const float4*)(kc + 16), k5 = *(const float4*)(kc + 20);
            float4 k6 = *(const float4*)(kc + 24), k7 = *(const float4*)(kc + 28);
            float s =
                q0.x * k0.x + q0.y * k0.y + q0.z * k0.z + q0.w * k0.w +
                q1.x * k1.x + q1.y * k1.y + q1.z * k1.z + q1.w * k1.w +
                q2.x * k2.x + q2.y * k2.y + q2.z * k2.z + q2.w * k2.w +
                q3.x * k3.x + q3.y * k3.y + q3.z * k3.z + q3.w * k3.w +
                q4.x * k4.x + q4.y * k4.y + q4.z * k4.z + q4.w * k4.w +
                q5.x * k5.x + q5.y * k5.y + q5.z * k5.z + q5.w * k5.w +
                q6.x * k6.x + q6.y * k6.y + q6.z * k6.z + q6.w * k6.w +
                q7.x * k7.x + q7.y * k7.y + q7.z * k7.z + q7.w * k7.w;
            Ss[r * 65 + c] = s * SCALE;
        }
    }
    __syncthreads();

    float mx = -1e30f;
    for (int c = l4; c < 64; c += 4) mx = fmaxf(mx, Ss[r * 65 + c]);
    mx = fmaxf(mx, __shfl_xor_sync(0xffffffffu, mx, 1));
    mx = fmaxf(mx, __shfl_xor_sync(0xffffffffu, mx, 2));
    float sum = 0.f;
    for (int c = l4; c < 64; c += 4) { float e = __expf(Ss[r * 65 + c] - mx); Ss[r * 65 + c] = e; sum += e; }
    sum += __shfl_xor_sync(0xffffffffu, sum, 1);
    sum += __shfl_xor_sync(0xffffffffu, sum, 2);
    float inv = 1.f / sum;
    __syncwarp();

    float o0[8];
#pragma unroll
    for (int j = 0; j < 8; j++) o0[j] = 0.f;
    for (int c = 0; c < 64; c++) {
        float p = Ss[r * 65 + c];
        float4 va = *(const float4*)&vsm[c * 36 + l4 * 8];
        float4 vb = *(const float4*)&vsm[c * 36 + l4 * 8 + 4];
        o0[0] += p * va.x; o0[1] += p * va.y; o0[2] += p * va.z; o0[3] += p * va.w;
        o0[4] += p * vb.x; o0[5] += p * vb.y; o0[6] += p * vb.z; o0[7] += p * vb.w;
    }
    size_t orow = ((size_t)(b * HH + wy * WSZ + (r >> 3)) * WW + wx * WSZ + (r & 7)) * DMODEL
                  + head * DHEAD + l4 * 8;
    __half2* op = (__half2*)(o + orow);
#pragma unroll
    for (int j = 0; j < 4; j++)
        op[j] = __halves2half2(__float2half_rn(o0[j * 2] * inv), __float2half_rn(o0[j * 2 + 1] * inv));
}

// ---------------- im2col (stride == kernel: pure permutation), fp16 ----------------
__global__ void im2col_kernel(const __half* __restrict__ y, __half* __restrict__ out)
{
    size_t idx = (size_t)blockIdx.x * 256 + threadIdx.x;
    if (idx >= (size_t)BATCH * NWIN * CONVK) return;
    int m = (int)(idx / CONVK), kk = (int)(idx % CONVK);
    int pos = kk / DMODEL, c = kk % DMODEL;
    int i = pos >> 3, j = pos & 7;
    int b = m / NWIN, win = m % NWIN, wy = win / 7, wx = win % 7;
    out[idx] = y[((size_t)(b * HH + wy * WSZ + i) * WW + wx * WSZ + j) * DMODEL + c];
}

// ---------------- split-K reduction + conv bias, fp16 out ----------------
__global__ void reduce_part_kernel(const float* __restrict__ part, const float* __restrict__ bias,
                                   __half* __restrict__ R)
{
    int idx = blockIdx.x * 256 + threadIdx.x;
    if (idx >= BATCH * NWIN * DMODEL) return;
    float s = bias[idx % DMODEL];
    const size_t stride = (size_t)BATCH * NWIN * DMODEL;
#pragma unroll
    for (int z = 0; z < SPLITK; z++) s += part[(size_t)z * stride + idx];
    R[idx] = __float2half_rn(s);
}

// ---------------- global attention: q fp16, kv fp32, out fp16 ----------------
__global__ __launch_bounds__(128) void gattn_kernel(const __half* __restrict__ q,
                                                    const float* __restrict__ kv,
                                                    __half* __restrict__ o)
{
    const int b = blockIdx.z, h = blockIdx.y;
    const int tid = threadIdx.x;
    __shared__ float ks[LRED * DHEAD], vs[LRED * DHEAD];
    for (int idx = tid; idx < LRED * DHEAD; idx += 128) {
        int l = idx >> 5, d = idx & 31;
        size_t base = (size_t)(b * LRED + l) * (2 * DMODEL) + h * DHEAD + d;
        ks[idx] = kv[base];
        vs[idx] = kv[base + DMODEL];
    }
    __syncthreads();
    int t = blockIdx.x * 128 + tid;
    if (t >= HH * WW) return;
    const __half2* qr = (const __half2*)(q + ((size_t)b * (HH * WW) + t) * DMODEL + h * DHEAD);
    float qv[32];
#pragma unroll
    for (int d = 0; d < 16; d++) {
        float2 f = __half22float2(qr[d]);
        qv[d * 2] = f.x; qv[d * 2 + 1] = f.y;
    }
    float s[LRED];
    float mx = -1e30f;
#pragma unroll
    for (int l = 0; l < LRED; l++) {
        float acc = 0.f;
#pragma unroll
        for (int d = 0; d < 32; d++) acc += qv[d] * ks[l * 32 + d];
        acc *= SCALE;
        s[l] = acc;
        mx = fmaxf(mx, acc);
    }
    float sum = 0.f;
#pragma unroll
    for (int l = 0; l < LRED; l++) { s[l] = __expf(s[l] - mx); sum += s[l]; }
    float inv = 1.f / sum;
    float ov[32];
#pragma unroll
    for (int d = 0; d < 32; d++) ov[d] = 0.f;
#pragma unroll
    for (int l = 0; l < LRED; l++) {
        float p = s[l];
#pragma unroll
        for (int d = 0; d < 32; d++) ov[d] += p * vs[l * 32 + d];
    }
    __half2* orow = (__half2*)(o + ((size_t)b * (HH * WW) + t) * DMODEL + h * DHEAD);
#pragma unroll
    for (int d = 0; d < 16; d++)
        orow[d] = __halves2half2(__float2half_rn(ov[d * 2] * inv), __float2half_rn(ov[d * 2 + 1] * inv));
}

// ---------------- host orchestration ----------------
static void launch_tconv(const float* W, __half* arr, int K, int N) {
    tconv_kernel<<<dim3(N / 32, K / 32), dim3(32, 8)>>>(W, arr, K, N);
}

extern "C" void kernel_launch(void* const* d_in, const int* in_sizes, int n_in,
                              void* d_out_v, int out_size)
{
    const float* x      = (const float*)d_in[0];
    const float* g1     = (const float*)d_in[1];
    const float* be1    = (const float*)d_in[2];
    const float* w_qkv  = (const float*)d_in[3];
    const float* b_qkv  = (const float*)d_in[4];
    const float* w_lo   = (const float*)d_in[5];
    const float* b_lo   = (const float*)d_in[6];
    const float* g2     = (const float*)d_in[7];
    const float* be2    = (const float*)d_in[8];
    const float* w_f1l  = (const float*)d_in[9];
    const float* b_f1l  = (const float*)d_in[10];
    const float* w_f2l  = (const float*)d_in[11];
    const float* b_f2l  = (const float*)d_in[12];
    const float* g3     = (const float*)d_in[13];
    const float* be3    = (const float*)d_in[14];
    const float* w_q    = (const float*)d_in[15];
    const float* w_kv   = (const float*)d_in[16];
    const float* conv_w = (const float*)d_in[17];
    const float* conv_b = (const float*)d_in[18];
    const float* w_go   = (const float*)d_in[19];
    const float* b_go   = (const float*)d_in[20];
    const float* g4     = (const float*)d_in[21];
    const float* be4    = (const float*)d_in[22];
    const float* w_f1g  = (const float*)d_in[23];
    const float* b_f1g  = (const float*)d_in[24];
    const float* w_f2g  = (const float*)d_in[25];
    const float* b_f2g  = (const float*)d_in[26];
    float* out = (float*)d_out_v;

    float *KV, *PART;
    __half *S0h, *S1h, *S2h, *H16, *S3h, *Rh;
    cudaGetSymbolAddress((void**)&KV, g_KV);
    cudaGetSymbolAddress((void**)&PART, g_PART);
    cudaGetSymbolAddress((void**)&S0h, g_S0h);
    cudaGetSymbolAddress((void**)&S1h, g_S1h);
    cudaGetSymbolAddress((void**)&S2h, g_S2h);
    cudaGetSymbolAddress((void**)&H16, g_H16);
    cudaGetSymbolAddress((void**)&S3h, g_S3h);
    cudaGetSymbolAddress((void**)&Rh,  g_Rh);
    __half *WqkvT, *WloT, *Wf1lT, *Wf2lT, *WqT, *WkvT, *WcvT, *WgoT, *Wf1gT, *Wf2gT;
    cudaGetSymbolAddress((void**)&WqkvT, g_qkvW);
    cudaGetSymbolAddress((void**)&WloT,  g_loW);
    cudaGetSymbolAddress((void**)&Wf1lT, g_f1lW);
    cudaGetSymbolAddress((void**)&Wf2lT, g_f2lW);
    cudaGetSymbolAddress((void**)&WqT,   g_qW);
    cudaGetSymbolAddress((void**)&WkvT,  g_kvW);
    cudaGetSymbolAddress((void**)&WcvT,  g_cvW);
    cudaGetSymbolAddress((void**)&WgoT,  g_goW);
    cudaGetSymbolAddress((void**)&Wf1gT, g_f1gW);
    cudaGetSymbolAddress((void**)&Wf2gT, g_f2gW);

    cudaFuncSetAttribute(hgemm<E_BIAS, float>,  cudaFuncAttributeMaxDynamicSharedMemorySize, HG_SMEM);
    cudaFuncSetAttribute(hgemm<E_BIAS, __half>, cudaFuncAttributeMaxDynamicSharedMemorySize, HG_SMEM);
    cudaFuncSetAttribute(hgemm<E_SILU, __half>, cudaFuncAttributeMaxDynamicSharedMemorySize, HG_SMEM);
    cudaFuncSetAttribute(hgemm<E_RES,  float>,  cudaFuncAttributeMaxDynamicSharedMemorySize, HG_SMEM);
    cudaFuncSetAttribute(hgemm<E_PART, float>,  cudaFuncAttributeMaxDynamicSharedMemorySize, HG_SMEM);

    const int MB  = NTOK / 128;                    // 392
    const int MBS = (BATCH * NWIN + 127) / 128;    // 7 (conv / kv GEMMs, M=784)
    dim3 blk(256);

    // launch order: our #4 (= likely overall #6 under ncu -s 5 -c 1) is the qkv hgemm
    launch_tconv(w_qkv,  WqkvT, DMODEL, QKVN);          // 1
    launch_tconv(w_lo,   WloT,  DMODEL, DMODEL);        // 2
    ln_kernel<<<NTOK / 8, 256>>>(x, g1, be1, S1h);      // 3

    // ---- block 1: local attention ----
    hgemm<E_BIAS, __half><<<dim3(QKVN / 128, MB, 1), blk, HG_SMEM>>>(   // 4
        S1h, WqkvT, b_qkv, nullptr, S0h, NTOK, DMODEL, QKVN, 1);
    wattn_kernel<<<BATCH * NWIN * NHEAD, 256>>>(S0h, S2h);
    hgemm<E_RES, float><<<dim3(DMODEL / 128, MB, 1), blk, HG_SMEM>>>(
        S2h, WloT, b_lo, x, out, NTOK, DMODEL, DMODEL, 1);

    // ---- block 2: local FFN ----
    launch_tconv(w_f1l,  Wf1lT, DMODEL, FFDIM);
    launch_tconv(w_f2l,  Wf2lT, FFDIM,  DMODEL);
    ln_kernel<<<NTOK / 8, 256>>>(out, g2, be2, S1h);
    hgemm<E_SILU, __half><<<dim3(FFDIM / 128, MB, 1), blk, HG_SMEM>>>(
        S1h, Wf1lT, b_f1l, nullptr, H16, NTOK, DMODEL, FFDIM, 1);
    hgemm<E_RES, float><<<dim3(DMODEL / 128, MB, 1), blk, HG_SMEM>>>(
        H16, Wf2lT, b_f2l, out, out, NTOK, FFDIM, DMODEL, 1);

    // remaining weight prep (before block 3 uses them)
    launch_tconv(w_q,    WqT,   DMODEL, DMODEL);
    launch_tconv(w_kv,   WkvT,  DMODEL, 2 * DMODEL);
    launch_tconv(conv_w, WcvT,  CONVK,  DMODEL);
    launch_tconv(w_go,   WgoT,  DMODEL, DMODEL);
    launch_tconv(w_f1g,  Wf1gT, DMODEL, FFDIM);
    launch_tconv(w_f2g,  Wf2gT, FFDIM,  DMODEL);

    // ---- block 3: global attention ----
    ln_kernel<<<NTOK / 8, 256>>>(out, g3, be3, S1h);
    hgemm<E_BIAS, __half><<<dim3(DMODEL / 128, MB, 1), blk, HG_SMEM>>>(
        S1h, WqT, nullptr, nullptr, S2h, NTOK, DMODEL, DMODEL, 1);
    {
        size_t tot = (size_t)BATCH * NWIN * CONVK;
        im2col_kernel<<<(unsigned)((tot + 255) / 256), 256>>>(S1h, S3h);
    }
    hgemm<E_PART, float><<<dim3(DMODEL / 128, MBS, SPLITK), blk, HG_SMEM>>>(
        S3h, WcvT, nullptr, nullptr, PART, BATCH * NWIN, CONVK, DMODEL, SPLITK);
    reduce_part_kernel<<<(BATCH * NWIN * DMODEL + 255) / 256, 256>>>(PART, conv_b, Rh);
    hgemm<E_BIAS, float><<<dim3((2 * DMODEL) / 128, MBS, 1), blk, HG_SMEM>>>(
        Rh, WkvT, nullptr, nullptr, KV, BATCH * LRED, DMODEL, 2 * DMODEL, 1);
    gattn_kernel<<<dim3((HH * WW + 127) / 128, NHEAD, BATCH), 128>>>(S2h, KV, H16);
    hgemm<E_RES, float><<<dim3(DMODEL / 128, MB, 1), blk, HG_SMEM>>>(
        H16, WgoT, b_go, out, out, NTOK, DMODEL, DMODEL, 1);

    // ---- block 4: global FFN ----
    ln_kernel<<<NTOK / 8, 256>>>(out, g4, be4, S1h);
    hgemm<E_SILU, __half><<<dim3(FFDIM / 128, MB, 1), blk, HG_SMEM>>>(
        S1h, Wf1gT, b_f1g, nullptr, H16, NTOK, DMODEL, FFDIM, 1);
    hgemm<E_RES, float><<<dim3(DMODEL / 128, MB, 1), blk, HG_SMEM>>>(
        H16, Wf2gT, b_f2g, out, out, NTOK, FFDIM, DMODEL, 1);
}